// round 5
// baseline (speedup 1.0000x reference)
#include <cuda_runtime.h>

// Shapes (fixed for this problem)
// B=2, N=512, M=512, Dq=Dk=Dv=128, De=64, H=8, O=32, OUT=128

#define BB 2
#define NN 512
#define MM 512
#define HH 8
#define OO 32
#define DE 64
#define DK 128
#define OUTC 128

// Scratch (no cudaMalloc allowed). ~4.5 MB total.
__device__ __align__(256) float g_qh[BB*NN*HH*OO];   // [b][n][h][o], q/sqrt(32) @ Wq
__device__ __align__(256) float g_qe[BB*NN*HH*DE];   // [b][n][h][j], qh @ Wk_edge^T
__device__ __align__(256) float g_kk[BB*MM*HH*OO];   // [b][m][h][o], key @ Wk_key
__device__ __align__(256) float g_v [BB*MM*HH*OO];   // [b][m][h][o], value @ Wv

// ---------------------------------------------------------------------------
// Prologue 1: qh = (query @ Wq)/sqrt(32);  qe[h,j] = sum_o qh[h,o]*Wk[h,128+j,o]
// grid 128 blocks x 256 thr, 8 rows (b,n) per block
// ---------------------------------------------------------------------------
__global__ __launch_bounds__(256) void proj_q_kernel(
    const float* __restrict__ query,
    const float* __restrict__ Wq,   // [H,128,32]
    const float* __restrict__ Wk)   // [H,192,32]
{
    __shared__ float q_s[8][128];
    __shared__ float qh_s[8][256];
    const int tid = threadIdx.x;
    const int row0 = blockIdx.x * 8;   // global row in [0, B*N)

    for (int idx = tid; idx < 8 * 128; idx += 256)
        q_s[idx >> 7][idx & 127] = query[row0 * 128 + idx];
    __syncthreads();

    const int h = tid >> 5, o = tid & 31;
    float acc[8];
#pragma unroll
    for (int r = 0; r < 8; r++) acc[r] = 0.f;
#pragma unroll 4
    for (int i = 0; i < 128; i++) {
        float w = Wq[(h * 128 + i) * 32 + o];
#pragma unroll
        for (int r = 0; r < 8; r++) acc[r] += q_s[r][i] * w;
    }
    const float scale = 0.17677669529663687f;  // 1/sqrt(32)
#pragma unroll
    for (int r = 0; r < 8; r++) {
        float val = acc[r] * scale;
        qh_s[r][tid] = val;
        g_qh[(row0 + r) * 256 + tid] = val;
    }
    __syncthreads();

    // qe: 512 outputs (8h x 64j), 2 per thread, 8 rows each
#pragma unroll
    for (int u = 0; u < 2; u++) {
        const int idx = tid + u * 256;
        const int hh = idx >> 6, j = idx & 63;
        float a2[8];
#pragma unroll
        for (int r = 0; r < 8; r++) a2[r] = 0.f;
#pragma unroll 4
        for (int oo = 0; oo < 32; oo++) {
            float w = Wk[(hh * 192 + 128 + j) * 32 + oo];
#pragma unroll
            for (int r = 0; r < 8; r++) a2[r] += qh_s[r][hh * 32 + oo] * w;
        }
#pragma unroll
        for (int r = 0; r < 8; r++) g_qe[(row0 + r) * 512 + idx] = a2[r];
    }
}

// ---------------------------------------------------------------------------
// Prologue 2: kk = key @ Wk[:, :128, :];  v = value @ Wv
// ---------------------------------------------------------------------------
__global__ __launch_bounds__(256) void proj_kv_kernel(
    const float* __restrict__ key,
    const float* __restrict__ value,
    const float* __restrict__ Wk,   // [H,192,32]
    const float* __restrict__ Wv)   // [H,128,32]
{
    __shared__ float k_s[8][128];
    __shared__ float v_s[8][128];
    const int tid = threadIdx.x;
    const int row0 = blockIdx.x * 8;

    for (int idx = tid; idx < 8 * 128; idx += 256) {
        k_s[idx >> 7][idx & 127] = key[row0 * 128 + idx];
        v_s[idx >> 7][idx & 127] = value[row0 * 128 + idx];
    }
    __syncthreads();

    const int h = tid >> 5, o = tid & 31;
    float ak[8], av[8];
#pragma unroll
    for (int r = 0; r < 8; r++) { ak[r] = 0.f; av[r] = 0.f; }
#pragma unroll 4
    for (int i = 0; i < 128; i++) {
        float wk = Wk[(h * 192 + i) * 32 + o];
        float wv = Wv[(h * 128 + i) * 32 + o];
#pragma unroll
        for (int r = 0; r < 8; r++) {
            ak[r] += k_s[r][i] * wk;
            av[r] += v_s[r][i] * wv;
        }
    }
#pragma unroll
    for (int r = 0; r < 8; r++) {
        g_kk[(row0 + r) * 256 + tid] = ak[r];
        g_v [(row0 + r) * 256 + tid] = av[r];
    }
}

// ---------------------------------------------------------------------------
// Main fused kernel: block = (b, 4 n-rows). 256 threads.
// logits -> softmax -> attn@v -> projection, all in one block.
// Dynamic smem: 20512 floats = 82048 bytes.
//   Ls   [32][512]  logits/probs  (row = n*8+h)
//   qh_s [4][256]
//   qe_s [4][512]
//   mh_s [4][256]
//   rsum [32]
// ---------------------------------------------------------------------------
#define SMEM_BYTES (20512 * 4)

__global__ __launch_bounds__(256, 2) void attn_kernel(
    const float* __restrict__ edge,   // [B,N,M,64]
    const float* __restrict__ P,      // [H,32,128]
    const float* __restrict__ bias,   // [128]
    float* __restrict__ out)          // [B,N,128]
{
    extern __shared__ float sm[];
    float* Ls   = sm;            // 16384
    float* qh_s = sm + 16384;    // 1024
    float* qe_s = sm + 17408;    // 2048
    float* mh_s = sm + 19456;    // 1024
    float* rsum = sm + 20480;    // 32

    const int tid = threadIdx.x;
    const int b  = blockIdx.x >> 7;
    const int n0 = (blockIdx.x & 127) * 4;
    const int baseRow = b * 512 + n0;   // first global n-row

    // Load qh (4 consecutive rows are contiguous) and qe
    for (int idx = tid; idx < 1024; idx += 256)
        qh_s[idx] = g_qh[baseRow * 256 + idx];
    for (int idx = tid; idx < 2048; idx += 256)
        qe_s[idx] = g_qe[baseRow * 512 + idx];
    __syncthreads();

    // ---- Phase B: logits[n][h][m] = edge-dot + qk-dot ----
    const float* kkb = g_kk + (size_t)b * 512 * 256;
    for (int m = tid; m < 512; m += 256) {
        float acc[4][8];
#pragma unroll
        for (int n = 0; n < 4; n++)
#pragma unroll
            for (int h = 0; h < 8; h++) acc[n][h] = 0.f;

#pragma unroll
        for (int n = 0; n < 4; n++) {
            const float4* ep = (const float4*)(edge +
                ((size_t)(baseRow + n) * 512 + m) * 64);
#pragma unroll 4
            for (int j4 = 0; j4 < 16; j4++) {
                float4 e = ep[j4];
#pragma unroll
                for (int h = 0; h < 8; h++) {
                    float4 qe4 = *(const float4*)&qe_s[n * 512 + h * 64 + j4 * 4];
                    acc[n][h] += e.x * qe4.x + e.y * qe4.y + e.z * qe4.z + e.w * qe4.w;
                }
            }
        }

        const float4* kp = (const float4*)(kkb + (size_t)m * 256);
#pragma unroll 8
        for (int t4 = 0; t4 < 64; t4++) {
            float4 kv = kp[t4];
            const int h = t4 >> 3;
#pragma unroll
            for (int n = 0; n < 4; n++) {
                float4 q4 = *(const float4*)&qh_s[n * 256 + t4 * 4];
                acc[n][h] += kv.x * q4.x + kv.y * q4.y + kv.z * q4.z + kv.w * q4.w;
            }
        }

#pragma unroll
        for (int n = 0; n < 4; n++)
#pragma unroll
            for (int h = 0; h < 8; h++)
                Ls[(n * 8 + h) * 512 + m] = acc[n][h];
    }
    __syncthreads();

    // ---- Phase C: softmax over m for each of 32 (n,h) rows ----
    {
        const int warp = tid >> 5, lane = tid & 31;
        for (int row = warp; row < 32; row += 8) {
            float* L = Ls + row * 512;
            float mx = -1e30f;
#pragma unroll
            for (int k = 0; k < 16; k++) mx = fmaxf(mx, L[lane + k * 32]);
#pragma unroll
            for (int s = 16; s > 0; s >>= 1)
                mx = fmaxf(mx, __shfl_xor_sync(0xffffffff, mx, s));
            float sum = 0.f;
#pragma unroll
            for (int k = 0; k < 16; k++) {
                float p = __expf(L[lane + k * 32] - mx);
                L[lane + k * 32] = p;
                sum += p;
            }
#pragma unroll
            for (int s = 16; s > 0; s >>= 1)
                sum += __shfl_xor_sync(0xffffffff, sum, s);
            if (lane == 0) rsum[row] = sum;
        }
    }
    __syncthreads();

    // ---- Phase D: mh[n][h][o] = sum_m p * v[b,m,h,o] ----
    {
        const int h = tid >> 5, o = tid & 31;
        const float* vp = g_v + (size_t)b * 512 * 256 + h * 32 + o;
        float acc[4] = {0.f, 0.f, 0.f, 0.f};
        for (int m = 0; m < 512; m += 4) {
            float v0 = vp[(m + 0) * 256];
            float v1 = vp[(m + 1) * 256];
            float v2 = vp[(m + 2) * 256];
            float v3 = vp[(m + 3) * 256];
#pragma unroll
            for (int n = 0; n < 4; n++) {
                float4 p4 = *(const float4*)&Ls[(n * 8 + h) * 512 + m];
                acc[n] += p4.x * v0 + p4.y * v1 + p4.z * v2 + p4.w * v3;
            }
        }
#pragma unroll
        for (int n = 0; n < 4; n++)
            mh_s[n * 256 + h * 32 + o] = acc[n] / rsum[n * 8 + h];
    }
    __syncthreads();

    // ---- Phase E: out[n][c] = mh[n] . P[:,:,c] + bias[c] ----
    {
        const int c = tid & 127;
        const int g = tid >> 7;   // 0/1 -> handles n=g and n=g+2
        float a0 = bias[c], a1 = bias[c];
#pragma unroll 4
        for (int ho = 0; ho < 256; ho++) {
            float p = P[ho * 128 + c];
            a0 += mh_s[g * 256 + ho] * p;
            a1 += mh_s[(g + 2) * 256 + ho] * p;
        }
        out[(size_t)(baseRow + g) * 128 + c] = a0;
        out[(size_t)(baseRow + g + 2) * 128 + c] = a1;
    }
}

// ---------------------------------------------------------------------------
extern "C" void kernel_launch(void* const* d_in, const int* in_sizes, int n_in,
                              void* d_out, int out_size) {
    const float* query = (const float*)d_in[0];
    const float* key   = (const float*)d_in[1];
    const float* value = (const float*)d_in[2];
    const float* edge  = (const float*)d_in[3];
    const float* Wq    = (const float*)d_in[4];
    const float* Wk    = (const float*)d_in[5];
    const float* Wv    = (const float*)d_in[6];
    const float* P     = (const float*)d_in[7];
    const float* bias  = (const float*)d_in[8];
    float* out = (float*)d_out;

    cudaFuncSetAttribute(attn_kernel,
                         cudaFuncAttributeMaxDynamicSharedMemorySize, SMEM_BYTES);

    proj_q_kernel<<<128, 256>>>(query, Wq, Wk);
    proj_kv_kernel<<<128, 256>>>(key, value, Wk, Wv);
    attn_kernel<<<256, 256, SMEM_BYTES>>>(edge, P, bias, out);
}